// round 1
// baseline (speedup 1.0000x reference)
#include <cuda_runtime.h>
#include <cuda_bf16.h>
#include <stdint.h>

#define M_ROWS   8192
#define DM       768
#define NF       16384
#define TOPK     64

// -------- scratch (no device allocs allowed) --------
__device__ int   g_tki[M_ROWS * TOPK];
__device__ float g_tkv[M_ROWS * TOPK];

// ============================================================
// Kernel 1: zero the codes region (537 MB)
// ============================================================
__global__ void zero_kernel(float4* __restrict__ p, size_t n4) {
    size_t i = (size_t)blockIdx.x * blockDim.x + threadIdx.x;
    size_t stride = (size_t)gridDim.x * blockDim.x;
    float4 z = make_float4(0.f, 0.f, 0.f, 0.f);
    for (; i < n4; i += stride) p[i] = z;
}

// ============================================================
// Kernel 2: encode GEMM  pre[m][n] = sum_k x[m][k] * W[n][k] + b[n]
// 128x128 block tile, BK=16, 8x8 per thread, 256 threads.
// ============================================================
#define BM 128
#define BN 128
#define BK 16

__global__ __launch_bounds__(256, 2)
void gemm_enc_kernel(const float* __restrict__ A,   // x [M, 768]
                     const float* __restrict__ B,   // W_enc [NF, 768]
                     const float* __restrict__ bias,
                     float* __restrict__ C) {       // pre [M, NF]
    __shared__ float As[BK][BM];
    __shared__ float Bs[BK][BN];

    const int tid = threadIdx.x;
    const int bm = blockIdx.y * BM;
    const int bn = blockIdx.x * BN;
    const int tx = tid & 15;       // 0..15
    const int ty = tid >> 4;       // 0..15

    const int lrow = tid >> 2;        // 0..63
    const int lc4  = (tid & 3) * 4;   // 0,4,8,12

    float acc[8][8];
#pragma unroll
    for (int i = 0; i < 8; i++)
#pragma unroll
        for (int j = 0; j < 8; j++) acc[i][j] = 0.f;

    for (int k0 = 0; k0 < DM; k0 += BK) {
#pragma unroll
        for (int h = 0; h < 2; h++) {
            int r = lrow + h * 64;
            float4 va = *(const float4*)(A + (size_t)(bm + r) * DM + k0 + lc4);
            As[lc4 + 0][r] = va.x; As[lc4 + 1][r] = va.y;
            As[lc4 + 2][r] = va.z; As[lc4 + 3][r] = va.w;
            float4 vb = *(const float4*)(B + (size_t)(bn + r) * DM + k0 + lc4);
            Bs[lc4 + 0][r] = vb.x; Bs[lc4 + 1][r] = vb.y;
            Bs[lc4 + 2][r] = vb.z; Bs[lc4 + 3][r] = vb.w;
        }
        __syncthreads();

#pragma unroll
        for (int kk = 0; kk < BK; kk++) {
            float a[8], b[8];
            float4 a0 = *(const float4*)(&As[kk][ty * 8 + 0]);
            float4 a1 = *(const float4*)(&As[kk][ty * 8 + 4]);
            float4 b0 = *(const float4*)(&Bs[kk][tx * 8 + 0]);
            float4 b1 = *(const float4*)(&Bs[kk][tx * 8 + 4]);
            a[0]=a0.x; a[1]=a0.y; a[2]=a0.z; a[3]=a0.w;
            a[4]=a1.x; a[5]=a1.y; a[6]=a1.z; a[7]=a1.w;
            b[0]=b0.x; b[1]=b0.y; b[2]=b0.z; b[3]=b0.w;
            b[4]=b1.x; b[5]=b1.y; b[6]=b1.z; b[7]=b1.w;
#pragma unroll
            for (int i = 0; i < 8; i++)
#pragma unroll
                for (int j = 0; j < 8; j++)
                    acc[i][j] += a[i] * b[j];
        }
        __syncthreads();
    }

    float bb[8];
#pragma unroll
    for (int j = 0; j < 8; j++) bb[j] = bias[bn + tx * 8 + j];

#pragma unroll
    for (int i = 0; i < 8; i++) {
        size_t off = (size_t)(bm + ty * 8 + i) * NF + bn + tx * 8;
        float4 o0, o1;
        o0.x = acc[i][0] + bb[0]; o0.y = acc[i][1] + bb[1];
        o0.z = acc[i][2] + bb[2]; o0.w = acc[i][3] + bb[3];
        o1.x = acc[i][4] + bb[4]; o1.y = acc[i][5] + bb[5];
        o1.z = acc[i][6] + bb[6]; o1.w = acc[i][7] + bb[7];
        *(float4*)(C + off)     = o0;
        *(float4*)(C + off + 4) = o1;
    }
}

// ============================================================
// Kernel 3: exact top-64 per row via 4-pass radix select on
// sign-flipped ordered uints, row cached in smem.
// Writes scatter into codes + compact (idx,val) scratch.
// ============================================================
__global__ __launch_bounds__(256)
void topk_kernel(const float* __restrict__ pre,
                 float* __restrict__ codes) {
    extern __shared__ unsigned su[];             // NF ordered keys (64 KB)
    __shared__ unsigned hist[256];
    __shared__ unsigned s_prefix, s_want;
    __shared__ unsigned cnt_gt, cnt_eq;

    const int row = blockIdx.x;
    const int tid = threadIdx.x;
    const float* p = pre + (size_t)row * NF;

    for (int i = tid; i < NF; i += 256) {
        unsigned b = __float_as_uint(p[i]);
        su[i] = (b & 0x80000000u) ? ~b : (b | 0x80000000u);
    }
    if (tid == 0) { s_prefix = 0u; s_want = TOPK; cnt_gt = 0u; cnt_eq = 0u; }
    __syncthreads();

#pragma unroll
    for (int shift = 24; shift >= 0; shift -= 8) {
        if (tid < 256) hist[tid] = 0u;
        __syncthreads();
        unsigned pref = s_prefix;
        for (int i = tid; i < NF; i += 256) {
            unsigned u = su[i];
            bool match = (shift == 24) || ((u >> (shift + 8)) == pref);
            if (match) atomicAdd(&hist[(u >> shift) & 255u], 1u);
        }
        __syncthreads();
        if (tid == 0) {
            unsigned want = s_want;
            unsigned cum = 0;
            for (int b = 255; b >= 0; b--) {
                unsigned c = hist[b];
                if (cum + c >= want) {
                    s_prefix = (pref << 8) | (unsigned)b;
                    s_want = want - cum;
                    break;
                }
                cum += c;
            }
        }
        __syncthreads();
    }

    const unsigned pivot = s_prefix;
    const unsigned E = s_want;            // # equal-to-pivot needed
    const unsigned G = TOPK - E;          // # strictly greater
    float* crow = codes + (size_t)row * NF;
    const int base = row * TOPK;

    for (int i = tid; i < NF; i += 256) {
        unsigned u = su[i];
        int slot = -1;
        if (u > pivot) {
            slot = (int)atomicAdd(&cnt_gt, 1u);
        } else if (u == pivot) {
            unsigned e = atomicAdd(&cnt_eq, 1u);
            if (e < E) slot = (int)(G + e);
        }
        if (slot >= 0) {
            float f = (u & 0x80000000u) ? __uint_as_float(u & 0x7fffffffu)
                                        : __uint_as_float(~u);
            crow[i] = f;
            g_tki[base + slot] = i;
            g_tkv[base + slot] = f;
        }
    }
}

// ============================================================
// Kernel 4: sparse decode  recon[row] = sum_k val_k * D[idx_k]
// One block per row, 256 threads x 3 columns each.
// ============================================================
__global__ __launch_bounds__(256)
void decode_kernel(const float* __restrict__ Dm,
                   float* __restrict__ recon) {
    __shared__ int   sidx[TOPK];
    __shared__ float sval[TOPK];
    const int row = blockIdx.x;
    const int tid = threadIdx.x;
    if (tid < TOPK) {
        sidx[tid] = g_tki[row * TOPK + tid];
        sval[tid] = g_tkv[row * TOPK + tid];
    }
    __syncthreads();

    const int c0 = tid, c1 = tid + 256, c2 = tid + 512;
    float acc0 = 0.f, acc1 = 0.f, acc2 = 0.f;
#pragma unroll 4
    for (int k = 0; k < TOPK; k++) {
        const float* dr = Dm + (size_t)sidx[k] * DM;
        float v = sval[k];
        acc0 += v * dr[c0];
        acc1 += v * dr[c1];
        acc2 += v * dr[c2];
    }
    float* r = recon + (size_t)row * DM;
    r[c0] = acc0; r[c1] = acc1; r[c2] = acc2;
}

// ============================================================
// launch
// ============================================================
extern "C" void kernel_launch(void* const* d_in, const int* in_sizes, int n_in,
                              void* d_out, int out_size) {
    const float* x    = (const float*)d_in[0];   // [8192, 768]
    const float* Wenc = (const float*)d_in[1];   // [16384, 768]
    const float* benc = (const float*)d_in[2];   // [16384]
    const float* Dm   = (const float*)d_in[3];   // [16384, 768]

    float* out   = (float*)d_out;
    float* recon = out;                                   // 8192*768
    float* codes = out + (size_t)M_ROWS * DM;             // 8192*16384
    float* pre   = codes + (size_t)M_ROWS * NF;           // 8192*16384

    // topk needs 64 KB dynamic smem
    cudaFuncSetAttribute(topk_kernel,
                         cudaFuncAttributeMaxDynamicSharedMemorySize,
                         NF * (int)sizeof(unsigned));

    // 1) zero codes region
    {
        size_t n4 = (size_t)M_ROWS * NF / 4;
        zero_kernel<<<16384, 256>>>((float4*)codes, n4);
    }
    // 2) encode GEMM -> pre
    {
        dim3 grid(NF / BN, M_ROWS / BM);
        gemm_enc_kernel<<<grid, 256>>>(x, Wenc, benc, pre);
    }
    // 3) top-64 select + scatter into codes
    topk_kernel<<<M_ROWS, 256, NF * sizeof(unsigned)>>>(pre, codes);
    // 4) sparse decode -> recon
    decode_kernel<<<M_ROWS, 256>>>(Dm, recon);
}